// round 2
// baseline (speedup 1.0000x reference)
#include <cuda_runtime.h>
#include <math.h>

#define BB 64
#define NN 1024
#define DD 512
#define KK 64
#define KG 80
#define ROWS (BB*NN)   // 65536

typedef unsigned long long u64t;

// Scratch (static device arrays — allowed)
__device__ float g_cs[DD*KK];           // BN-scaled clusters (real 64 cols)
__device__ float g_assign[ROWS*KK];     // softmax assignment (16.8 MB)
__device__ float g_asum_p[512*KK];      // per-assign-block column partials
__device__ float g_ss[BB*4*KK];         // per-(b,dtile) sum-of-squares partials
__device__ float g_scale[BB*KK];        // final per-(b,k) scale

// ---- packed f32x2 helpers (sm_103a FFMA2) --------------------------------
__device__ __forceinline__ u64t ffma2(u64t a, u64t b, u64t c) {
    u64t d;
    asm("fma.rn.f32x2 %0, %1, %2, %3;" : "=l"(d) : "l"(a), "l"(b), "l"(c));
    return d;
}
__device__ __forceinline__ u64t pack2(float lo, float hi) {
    u64t d;
    asm("mov.b64 %0, {%1, %2};" : "=l"(d) : "f"(lo), "f"(hi));
    return d;
}
__device__ __forceinline__ float2 unpack2(u64t v) {
    float2 r;
    asm("mov.b64 {%0, %1}, %2;" : "=f"(r.x), "=f"(r.y) : "l"(v));
    return r;
}

// ---------------------------------------------------------------------------
// K1: fold BN scale into cluster columns (ghosts dropped; BN shift unused).
// ---------------------------------------------------------------------------
__global__ void k_prep(const float* __restrict__ clusters,
                       const float* __restrict__ bn_w,
                       const float* __restrict__ bn_var) {
    int i = blockIdx.x * 256 + threadIdx.x;   // covers DD*KK
    int d = i >> 6;
    int k = i & 63;
    float s = bn_w[k] * rsqrtf(bn_var[k] + 1e-5f);
    g_cs[i] = clusters[d * KG + k] * s;
}

// ---------------------------------------------------------------------------
// K2: logits GEMM [65536,512]x[512,64] + row softmax + column-sum partials.
// Block: 128 rows x 64 k, 256 threads. Thread: 4 rows x 8 k (4 f32x2 pairs).
// tx = tid&7 -> k8 = tx*8 ; ty = tid>>3 -> rows ty*4..+3.
// ---------------------------------------------------------------------------
__global__ __launch_bounds__(256) void k_assign(const float* __restrict__ x) {
    __shared__ float xs[128 * 36];   // row stride 36: float4-aligned, pad
    __shared__ float cs[32 * 64];
    __shared__ float red[8 * 64];

    const int tid = threadIdx.x;
    const int tx  = tid & 7;
    const int ty  = tid >> 3;        // 0..31
    const int k8  = tx * 8;
    const long rowbase = (long)blockIdx.x * 128;

    u64t acc[4][4];
#pragma unroll
    for (int i = 0; i < 4; i++)
#pragma unroll
        for (int p = 0; p < 4; p++) acc[i][p] = 0ull;

    for (int d0 = 0; d0 < DD; d0 += 32) {
        // x tile: 128 rows x 32 dd = 1024 float4, 4 per thread (coalesced)
#pragma unroll
        for (int j = 0; j < 4; j++) {
            int fidx = tid + j * 256;
            int r = fidx >> 3, c4 = (fidx & 7) * 4;
            *(float4*)&xs[r * 36 + c4] =
                *(const float4*)&x[(rowbase + r) * DD + d0 + c4];
        }
        // cluster tile: 32 x 64 = 512 float4, 2 per thread
#pragma unroll
        for (int j = 0; j < 2; j++) {
            int fidx = tid + j * 256;
            int r = fidx >> 4, c4 = (fidx & 15) * 4;
            *(float4*)&cs[r * 64 + c4] = *(const float4*)&g_cs[(d0 + r) * KK + c4];
        }
        __syncthreads();

#pragma unroll
        for (int dd = 0; dd < 32; dd++) {
            const ulonglong2 cA = *(const ulonglong2*)&cs[dd * 64 + k8];      // pairs 0,1
            const ulonglong2 cB = *(const ulonglong2*)&cs[dd * 64 + k8 + 4];  // pairs 2,3
#pragma unroll
            for (int i = 0; i < 4; i++) {
                const float xv = xs[(ty * 4 + i) * 36 + dd];
                const u64t xd = pack2(xv, xv);
                acc[i][0] = ffma2(xd, cA.x, acc[i][0]);
                acc[i][1] = ffma2(xd, cA.y, acc[i][1]);
                acc[i][2] = ffma2(xd, cB.x, acc[i][2]);
                acc[i][3] = ffma2(xd, cB.y, acc[i][3]);
            }
        }
        __syncthreads();
    }

    // --- softmax over the 64 real clusters (k split across 8 lanes) ---
    float colp[8];
#pragma unroll
    for (int j = 0; j < 8; j++) colp[j] = 0.f;

#pragma unroll
    for (int i = 0; i < 4; i++) {
        float f[8];
#pragma unroll
        for (int p = 0; p < 4; p++) {
            float2 t = unpack2(acc[i][p]);
            f[2 * p] = t.x; f[2 * p + 1] = t.y;
        }
        float m = f[0];
#pragma unroll
        for (int j = 1; j < 8; j++) m = fmaxf(m, f[j]);
        m = fmaxf(m, __shfl_xor_sync(0xffffffffu, m, 1));
        m = fmaxf(m, __shfl_xor_sync(0xffffffffu, m, 2));
        m = fmaxf(m, __shfl_xor_sync(0xffffffffu, m, 4));
        float s = 0.f;
#pragma unroll
        for (int j = 0; j < 8; j++) { f[j] = __expf(f[j] - m); s += f[j]; }
        s += __shfl_xor_sync(0xffffffffu, s, 1);
        s += __shfl_xor_sync(0xffffffffu, s, 2);
        s += __shfl_xor_sync(0xffffffffu, s, 4);
        const float inv = 1.f / s;
#pragma unroll
        for (int j = 0; j < 8; j++) { f[j] *= inv; colp[j] += f[j]; }

        const long row = rowbase + ty * 4 + i;
        *(float4*)&g_assign[row * KK + k8]     = make_float4(f[0], f[1], f[2], f[3]);
        *(float4*)&g_assign[row * KK + k8 + 4] = make_float4(f[4], f[5], f[6], f[7]);
    }

    // --- column-sum partials (a_sum precursor), free in registers ---
#pragma unroll
    for (int j = 0; j < 8; j++) {
        colp[j] += __shfl_xor_sync(0xffffffffu, colp[j], 8);
        colp[j] += __shfl_xor_sync(0xffffffffu, colp[j], 16);
    }
    const int lane = tid & 31, warp = tid >> 5;
    if (lane < 8) {
#pragma unroll
        for (int j = 0; j < 8; j++) red[warp * 64 + lane * 8 + j] = colp[j];
    }
    __syncthreads();
    if (tid < 64) {
        float s = 0.f;
#pragma unroll
        for (int w = 0; w < 8; w++) s += red[w * 64 + tid];
        g_asum_p[blockIdx.x * 64 + tid] = s;
    }
}

// ---------------------------------------------------------------------------
// K3: per-batch X^T @ A  (vlad) + fused residual + intra-norm sumsq partials.
// Grid (4 dtiles, 64 b). Block: 128 d x 64 k, 256 threads, thread 4d x 8k.
// ---------------------------------------------------------------------------
__global__ __launch_bounds__(256) void k_vlad(const float* __restrict__ x,
                                              const float* __restrict__ c2,
                                              float* __restrict__ out) {
    __shared__ float xs[16 * 132];   // stride 132: 16B aligned rows
    __shared__ float as[16 * 64];
    __shared__ float asum_s[64];
    __shared__ float red[8 * 64];

    const int tid = threadIdx.x;
    const int tx  = tid & 7;
    const int ty  = tid >> 3;        // 0..31
    const int k8  = tx * 8;
    const int b   = blockIdx.y;
    const int d0  = blockIdx.x * 128;

    if (tid < 64) {
        float s = 0.f;
#pragma unroll
        for (int p = 0; p < 8; p++) s += g_asum_p[(b * 8 + p) * 64 + tid];
        asum_s[tid] = s;
    }

    u64t acc[4][4];
#pragma unroll
    for (int i = 0; i < 4; i++)
#pragma unroll
        for (int p = 0; p < 4; p++) acc[i][p] = 0ull;

    const float* xb = x        + (long)b * NN * DD;
    const float* ab = g_assign + (long)b * NN * KK;

    for (int n0 = 0; n0 < NN; n0 += 16) {
        // xs: 16 n x 128 d = 512 float4, 2 per thread
#pragma unroll
        for (int j = 0; j < 2; j++) {
            int fidx = tid + j * 256;
            int r = fidx >> 5, c4 = (fidx & 31) * 4;
            *(float4*)&xs[r * 132 + c4] =
                *(const float4*)&xb[(n0 + r) * DD + d0 + c4];
        }
        // as: 16 n x 64 k = 256 float4, 1 per thread
        {
            int r = tid >> 4, c4 = (tid & 15) * 4;
            *(float4*)&as[r * 64 + c4] = *(const float4*)&ab[(n0 + r) * KK + c4];
        }
        __syncthreads();

#pragma unroll
        for (int nn = 0; nn < 16; nn++) {
            const ulonglong2 aA = *(const ulonglong2*)&as[nn * 64 + k8];
            const ulonglong2 aB = *(const ulonglong2*)&as[nn * 64 + k8 + 4];
#pragma unroll
            for (int i = 0; i < 4; i++) {
                const float xv = xs[nn * 132 + ty * 4 + i];
                const u64t xd = pack2(xv, xv);
                acc[i][0] = ffma2(xd, aA.x, acc[i][0]);
                acc[i][1] = ffma2(xd, aA.y, acc[i][1]);
                acc[i][2] = ffma2(xd, aB.x, acc[i][2]);
                acc[i][3] = ffma2(xd, aB.y, acc[i][3]);
            }
        }
        __syncthreads();
    }

    // --- epilogue: residual, write, sumsq partials ---
    float asv[8];
#pragma unroll
    for (int j = 0; j < 8; j++) asv[j] = asum_s[k8 + j];
    float ss[8];
#pragma unroll
    for (int j = 0; j < 8; j++) ss[j] = 0.f;

#pragma unroll
    for (int i = 0; i < 4; i++) {
        const int d = d0 + ty * 4 + i;
        float f[8];
#pragma unroll
        for (int p = 0; p < 4; p++) {
            float2 t = unpack2(acc[i][p]);
            f[2 * p] = t.x; f[2 * p + 1] = t.y;
        }
        const float4 ca = *(const float4*)&c2[d * KK + k8];
        const float4 cb = *(const float4*)&c2[d * KK + k8 + 4];
        f[0] -= asv[0] * ca.x;  f[1] -= asv[1] * ca.y;
        f[2] -= asv[2] * ca.z;  f[3] -= asv[3] * ca.w;
        f[4] -= asv[4] * cb.x;  f[5] -= asv[5] * cb.y;
        f[6] -= asv[6] * cb.z;  f[7] -= asv[7] * cb.w;
#pragma unroll
        for (int j = 0; j < 8; j++) ss[j] += f[j] * f[j];

        float* op = out + ((long)b * DD + d) * KK + k8;
        *(float4*)op       = make_float4(f[0], f[1], f[2], f[3]);
        *(float4*)(op + 4) = make_float4(f[4], f[5], f[6], f[7]);
    }

#pragma unroll
    for (int j = 0; j < 8; j++) {
        ss[j] += __shfl_xor_sync(0xffffffffu, ss[j], 8);
        ss[j] += __shfl_xor_sync(0xffffffffu, ss[j], 16);
    }
    const int lane = tid & 31, warp = tid >> 5;
    if (lane < 8) {
#pragma unroll
        for (int j = 0; j < 8; j++) red[warp * 64 + lane * 8 + j] = ss[j];
    }
    __syncthreads();
    if (tid < 64) {
        float s = 0.f;
#pragma unroll
        for (int w = 0; w < 8; w++) s += red[w * 64 + tid];
        g_ss[(b * 4 + blockIdx.x) * 64 + tid] = s;
    }
}

// ---------------------------------------------------------------------------
// K4: tiny per-(b,k) scale factors (intra-norm * global-norm combined).
// ---------------------------------------------------------------------------
__global__ __launch_bounds__(64) void k_scale1() {
    __shared__ float warpsum[2];
    const int b = blockIdx.x, t = threadIdx.x;
    float s = 0.f;
#pragma unroll
    for (int p = 0; p < 4; p++) s += g_ss[(b * 4 + p) * 64 + t];
    const float n   = sqrtf(s);
    const float csv = 1.f / fmaxf(n, 1e-12f);
    const float nu  = n * csv;
    float w = nu * nu;
#pragma unroll
    for (int o = 16; o; o >>= 1) w += __shfl_xor_sync(0xffffffffu, w, o);
    if ((t & 31) == 0) warpsum[t >> 5] = w;
    __syncthreads();
    const float g = sqrtf(warpsum[0] + warpsum[1]);
    g_scale[b * 64 + t] = csv / fmaxf(g, 1e-12f);
}

// ---------------------------------------------------------------------------
// K5: in-place scale of out (high parallelism: 512 blocks).
// ---------------------------------------------------------------------------
__global__ __launch_bounds__(256) void k_scale2(float* __restrict__ out) {
    __shared__ float sc[64];
    const int b = blockIdx.y, dt = blockIdx.x;
    if (threadIdx.x < 64) sc[threadIdx.x] = g_scale[b * 64 + threadIdx.x];
    __syncthreads();
    float4* p = (float4*)(out + ((long)b * DD + dt * 64) * KK);
#pragma unroll
    for (int j = 0; j < 4; j++) {
        const int idx = threadIdx.x + j * 256;   // 0..1023 float4 per block
        const int k4 = (idx & 15) * 4;
        float4 v = p[idx];
        v.x *= sc[k4];     v.y *= sc[k4 + 1];
        v.z *= sc[k4 + 2]; v.w *= sc[k4 + 3];
        p[idx] = v;
    }
}

// ---------------------------------------------------------------------------
extern "C" void kernel_launch(void* const* d_in, const int* in_sizes, int n_in,
                              void* d_out, int out_size) {
    const float* x        = (const float*)d_in[0];  // [64,1024,512]
    const float* clusters = (const float*)d_in[1];  // [512,80]
    const float* bn_w     = (const float*)d_in[2];  // [80]
    const float* bn_var   = (const float*)d_in[5];  // [80]
    const float* c2       = (const float*)d_in[6];  // [1,512,64]
    float* out = (float*)d_out;

    k_prep<<<(DD * KK) / 256, 256>>>(clusters, bn_w, bn_var);
    k_assign<<<ROWS / 128, 256>>>(x);
    dim3 gv(4, BB);
    k_vlad<<<gv, 256>>>(x, c2, out);
    k_scale1<<<BB, 64>>>();
    dim3 gs(8, BB);
    k_scale2<<<gs, 256>>>(out);
}

// round 3
// speedup vs baseline: 1.2189x; 1.2189x over previous
#include <cuda_runtime.h>
#include <math.h>

#define BB 64
#define NN 1024
#define DD 512
#define KK 64
#define KG 80
#define ROWS (BB*NN)   // 65536

// Scratch (static device arrays — allowed)
__device__ float g_cs[DD*KK];          // BN-scaled clusters (real 64 cols)
__device__ float g_assign[ROWS*KK];    // softmax assignment (16.8 MB)
__device__ float g_ss[BB*8*KK];        // per-(b,dtile) sum-of-squares partials

// ---------------------------------------------------------------------------
// K1: fold BN scale into cluster columns (ghosts dropped before softmax in
// the reference; BN shift computed-but-unused there).
// ---------------------------------------------------------------------------
__global__ void k_prep(const float* __restrict__ clusters,
                       const float* __restrict__ bn_w,
                       const float* __restrict__ bn_var) {
    int i = blockIdx.x * 256 + threadIdx.x;   // covers DD*KK
    int d = i >> 6;
    int k = i & 63;
    float s = bn_w[k] * rsqrtf(bn_var[k] + 1e-5f);
    g_cs[i] = clusters[d * KG + k] * s;
}

// ---------------------------------------------------------------------------
// K2: logits GEMM [65536,512]x[512,64] fused with row softmax.
// 128 threads/block, 1 thread = 1 row, 64 fp32 accumulators. (R1 known-good)
// ---------------------------------------------------------------------------
__global__ __launch_bounds__(128) void k_assign(const float* __restrict__ x) {
    __shared__ float xs[128][33];     // padded: conflict-free
    __shared__ float cs[32][64];      // broadcast reads

    const int tid  = threadIdx.x;
    const int warp = tid >> 5;
    const int lane = tid & 31;
    const long rowbase = (long)blockIdx.x * 128;

    float acc[64];
#pragma unroll
    for (int k = 0; k < 64; k++) acc[k] = 0.f;

    for (int d0 = 0; d0 < DD; d0 += 32) {
#pragma unroll
        for (int r = warp; r < 128; r += 4)
            xs[r][lane] = x[(rowbase + r) * DD + d0 + lane];
#pragma unroll
        for (int i = tid; i < 32 * 64; i += 128)
            cs[i >> 6][i & 63] = g_cs[(d0 + (i >> 6)) * KK + (i & 63)];
        __syncthreads();

#pragma unroll
        for (int dd = 0; dd < 32; dd++) {
            const float xv = xs[tid][dd];
#pragma unroll
            for (int k = 0; k < 64; k++)
                acc[k] = fmaf(xv, cs[dd][k], acc[k]);
        }
        __syncthreads();
    }

    // softmax over the 64 real clusters
    float m = acc[0];
#pragma unroll
    for (int k = 1; k < 64; k++) m = fmaxf(m, acc[k]);
    float s = 0.f;
#pragma unroll
    for (int k = 0; k < 64; k++) { acc[k] = __expf(acc[k] - m); s += acc[k]; }
    const float inv = 1.f / s;
#pragma unroll
    for (int k = 0; k < 64; k++) acc[k] *= inv;

    float4* outp = (float4*)&g_assign[(rowbase + tid) * KK];
#pragma unroll
    for (int k = 0; k < 64; k += 4)
        outp[k >> 2] = make_float4(acc[k], acc[k + 1], acc[k + 2], acc[k + 3]);
}

// ---------------------------------------------------------------------------
// K3: per-batch einsum  vlad[b,d,k] = sum_n a[b,n,k]*x[b,n,d]  (X^T @ A),
// fused with: a_sum accumulation (assignment tile already in smem),
// residual subtraction, output write, and intra-norm sum-of-squares partials.
// Block = 64x64 output tile, 256 threads, 4x4 register blocking. (R1 core)
// ---------------------------------------------------------------------------
__global__ __launch_bounds__(256) void k_vlad(const float* __restrict__ x,
                                              const float* __restrict__ c2,
                                              float* __restrict__ out) {
    __shared__ float xs[16][68];
    __shared__ float as[16][68];
    __shared__ float asp[4][64];      // a_sum quarter-partials
    __shared__ float asum_s[64];
    __shared__ float red[16][64];

    const int b  = blockIdx.y;
    const int d0 = blockIdx.x * 64;
    const int tid = threadIdx.x;
    const int tx = tid & 15;       // k sub-tile
    const int ty = tid >> 4;       // d sub-tile

    const float* xb = x        + (long)b * NN * DD;
    const float* ab = g_assign + (long)b * NN * KK;

    float acc[4][4];
#pragma unroll
    for (int i = 0; i < 4; i++)
#pragma unroll
        for (int j = 0; j < 4; j++) acc[i][j] = 0.f;

    // a_sum accumulation: thread sums column (tid&63), rows quarter (tid>>6)
    const int ak = tid & 63;
    const int aq = tid >> 6;
    float asum_l = 0.f;

    const int ln = tid >> 4;          // row within tile to load
    const int ld = (tid & 15) * 4;    // float4 column

    for (int n0 = 0; n0 < NN; n0 += 16) {
        *(float4*)&xs[ln][ld] = *(const float4*)&xb[(n0 + ln) * DD + d0 + ld];
        *(float4*)&as[ln][ld] = *(const float4*)&ab[(n0 + ln) * KK + ld];
        __syncthreads();

#pragma unroll
        for (int q = 0; q < 4; q++)
            asum_l += as[aq * 4 + q][ak];

#pragma unroll
        for (int nn = 0; nn < 16; nn++) {
            const float4 xv = *(const float4*)&xs[nn][ty * 4];
            const float4 av = *(const float4*)&as[nn][tx * 4];
            const float xr[4] = {xv.x, xv.y, xv.z, xv.w};
            const float ar[4] = {av.x, av.y, av.z, av.w};
#pragma unroll
            for (int i = 0; i < 4; i++)
#pragma unroll
                for (int j = 0; j < 4; j++)
                    acc[i][j] = fmaf(xr[i], ar[j], acc[i][j]);
        }
        __syncthreads();
    }

    // finalize a_sum
    asp[aq][ak] = asum_l;
    __syncthreads();
    if (tid < 64)
        asum_s[tid] = asp[0][tid] + asp[1][tid] + asp[2][tid] + asp[3][tid];
    __syncthreads();

    // epilogue: residual, write out, sum-of-squares partials
    const float4 asv4 = *(const float4*)&asum_s[tx * 4];
    const float asv[4] = {asv4.x, asv4.y, asv4.z, asv4.w};
    float ss[4] = {0.f, 0.f, 0.f, 0.f};

    float* ob = out + ((long)b * DD + d0) * KK;
#pragma unroll
    for (int i = 0; i < 4; i++) {
        const int d = d0 + ty * 4 + i;
        const float4 cv = *(const float4*)&c2[d * KK + tx * 4];
        const float cr[4] = {cv.x, cv.y, cv.z, cv.w};
        float v[4];
#pragma unroll
        for (int j = 0; j < 4; j++) {
            v[j] = acc[i][j] - asv[j] * cr[j];
            ss[j] += v[j] * v[j];
        }
        *(float4*)&ob[(ty * 4 + i) * KK + tx * 4] =
            make_float4(v[0], v[1], v[2], v[3]);
    }

    // reduce ss over the 16 d-subtiles
#pragma unroll
    for (int j = 0; j < 4; j++) red[ty][tx * 4 + j] = ss[j];
    __syncthreads();
    if (tid < 64) {
        float s = 0.f;
#pragma unroll
        for (int t = 0; t < 16; t++) s += red[t][tid];
        g_ss[(b * 8 + blockIdx.x) * 64 + tid] = s;
    }
}

// ---------------------------------------------------------------------------
// K4: per-(b,dtile) block recomputes the (tiny) per-batch scale factors and
// rescales its 64x64 region of out in place. 512 blocks -> full BW.
// ---------------------------------------------------------------------------
__global__ __launch_bounds__(256) void k_scale(float* __restrict__ out) {
    __shared__ float sc[64];
    __shared__ float nu2[64];
    __shared__ float wsum[2];

    const int b  = blockIdx.y;
    const int dt = blockIdx.x;
    const int t  = threadIdx.x;

    if (t < 64) {
        float s2 = 0.f;
#pragma unroll
        for (int p = 0; p < 8; p++) s2 += g_ss[(b * 8 + p) * 64 + t];
        const float n  = sqrtf(s2);
        const float cv = 1.f / fmaxf(n, 1e-12f);
        const float nu = n * cv;
        sc[t]  = cv;
        nu2[t] = nu * nu;
    }
    __syncthreads();
    if (t < 64) {
        float w = nu2[t];
#pragma unroll
        for (int o = 16; o; o >>= 1) w += __shfl_xor_sync(0xffffffffu, w, o);
        if ((t & 31) == 0) wsum[t >> 5] = w;
    }
    __syncthreads();
    const float ginv = 1.f / fmaxf(sqrtf(wsum[0] + wsum[1]), 1e-12f);

    float4* p = (float4*)(out + ((long)b * DD + dt * 64) * KK);
#pragma unroll
    for (int j = 0; j < 4; j++) {
        const int idx = t + j * 256;        // 0..1023 float4
        const int k4 = (idx & 15) * 4;
        float4 v = p[idx];
        v.x *= sc[k4]     * ginv;
        v.y *= sc[k4 + 1] * ginv;
        v.z *= sc[k4 + 2] * ginv;
        v.w *= sc[k4 + 3] * ginv;
        p[idx] = v;
    }
}

// ---------------------------------------------------------------------------
extern "C" void kernel_launch(void* const* d_in, const int* in_sizes, int n_in,
                              void* d_out, int out_size) {
    const float* x        = (const float*)d_in[0];  // [64,1024,512]
    const float* clusters = (const float*)d_in[1];  // [512,80]
    const float* bn_w     = (const float*)d_in[2];  // [80]
    const float* bn_var   = (const float*)d_in[5];  // [80]
    const float* c2       = (const float*)d_in[6];  // [1,512,64]
    float* out = (float*)d_out;

    k_prep<<<(DD * KK) / 256, 256>>>(clusters, bn_w, bn_var);
    k_assign<<<ROWS / 128, 128>>>(x);
    dim3 gv(DD / 64, BB);
    k_vlad<<<gv, 256>>>(x, c2, out);
    dim3 gs(DD / 64, BB);
    k_scale<<<gs, 256>>>(out);
}

// round 6
// speedup vs baseline: 2.1794x; 1.7880x over previous
#include <cuda_runtime.h>
#include <cuda_bf16.h>
#include <cstdint>
#include <math.h>

#define BB 64
#define NN 1024
#define DD 512
#define KK 64
#define KG 80
#define ROWS (BB*NN)   // 65536

// Scratch (static device arrays — allowed)
__device__ uint32_t g_cbh[KK*256];        // cT[k][d] bf16-hi, d-pairs packed
__device__ uint32_t g_cbl[KK*256];        // bf16-lo residual
__device__ uint32_t g_aTh[BB*KK*(NN/2)];  // aT[b][k][n] bf16-hi packed (8.4MB)
__device__ uint32_t g_aTl[BB*KK*(NN/2)];  // bf16-lo (8.4MB)
__device__ float    g_asum_p[512*KK];     // per-assign-block column partials
__device__ float    g_ss[BB*8*KK];        // per-(b,dtile) sumsq partials

// ---------------- helpers -------------------------------------------------
__device__ __forceinline__ void split2(float a, float b, uint32_t& h, uint32_t& l) {
    __nv_bfloat16 a1 = __float2bfloat16_rn(a);
    __nv_bfloat16 b1 = __float2bfloat16_rn(b);
    float ar = a - __bfloat162float(a1);
    float br = b - __bfloat162float(b1);
    __nv_bfloat16 a2 = __float2bfloat16_rn(ar);
    __nv_bfloat16 b2 = __float2bfloat16_rn(br);
    h = ((uint32_t)__bfloat16_as_ushort(b1) << 16) | __bfloat16_as_ushort(a1);
    l = ((uint32_t)__bfloat16_as_ushort(b2) << 16) | __bfloat16_as_ushort(a2);
}

__device__ __forceinline__ void mma16816(float* d, uint32_t a0, uint32_t a1,
                                         uint32_t a2, uint32_t a3,
                                         uint32_t b0, uint32_t b1) {
    asm volatile(
        "mma.sync.aligned.m16n8k16.row.col.f32.bf16.bf16.f32 "
        "{%0,%1,%2,%3}, {%4,%5,%6,%7}, {%8,%9}, {%0,%1,%2,%3};"
        : "+f"(d[0]), "+f"(d[1]), "+f"(d[2]), "+f"(d[3])
        : "r"(a0), "r"(a1), "r"(a2), "r"(a3), "r"(b0), "r"(b1));
}

// ---------------------------------------------------------------------------
// K1: BN-fold + transpose + bf16 hi/lo split+pack of clusters: cT[k][d].
// ---------------------------------------------------------------------------
__global__ void k_prep(const float* __restrict__ clusters,
                       const float* __restrict__ bn_w,
                       const float* __restrict__ bn_var) {
    int i = blockIdx.x * 256 + threadIdx.x;   // 0..16383 = 64k x 256 dpairs
    int k = i >> 8;
    int p = i & 255;
    float s = bn_w[k] * rsqrtf(bn_var[k] + 1e-5f);
    float c0 = clusters[(2 * p)     * KG + k] * s;
    float c1 = clusters[(2 * p + 1) * KG + k] * s;
    uint32_t h, l;
    split2(c0, c1, h, l);
    g_cbh[i] = h;
    g_cbl[i] = l;
}

// ---------------------------------------------------------------------------
// K2: logits GEMM [65536,512]x[512,64] via mma.sync bf16x3 + softmax.
// Block 128 threads (4 warps), 128 rows. Warp: 2 m16 tiles x 8 n8 tiles.
// Writes aT (transposed, bf16 hi/lo packed) + a_sum partials.
// ---------------------------------------------------------------------------
__global__ __launch_bounds__(128) void k_assign(const float* __restrict__ x) {
    __shared__ uint32_t xh32[128 * 17], xl32[128 * 17];
    __shared__ uint32_t bh32[64 * 17],  bl32[64 * 17];
    __shared__ float    redp[4 * 64];

    const int tid  = threadIdx.x;
    const int w    = tid >> 5;
    const int lane = tid & 31;
    const int g    = lane >> 2;
    const int tig  = lane & 3;
    const long rowbase = (long)blockIdx.x * 128;
    const int  b    = blockIdx.x >> 3;          // 8 blocks per batch
    const int  nb2  = (blockIdx.x & 7) * 64;    // first n-pair within batch

    float acc[2][8][4];
#pragma unroll
    for (int mt = 0; mt < 2; mt++)
#pragma unroll
        for (int j = 0; j < 8; j++)
#pragma unroll
            for (int q = 0; q < 4; q++) acc[mt][j][q] = 0.f;

    for (int d0 = 0; d0 < DD; d0 += 32) {
        // x tile: 128 rows x 32 d, split+pack
#pragma unroll
        for (int j = 0; j < 8; j++) {
            const int f = tid + j * 128;
            const int r = f >> 3, c4 = (f & 7) * 4;
            const float4 v = *(const float4*)&x[(rowbase + r) * DD + d0 + c4];
            uint32_t h0, l0, h1, l1;
            split2(v.x, v.y, h0, l0);
            split2(v.z, v.w, h1, l1);
            xh32[r * 17 + (c4 >> 1)]     = h0;
            xh32[r * 17 + (c4 >> 1) + 1] = h1;
            xl32[r * 17 + (c4 >> 1)]     = l0;
            xl32[r * 17 + (c4 >> 1) + 1] = l1;
        }
        // cluster tile: 64 k x 16 dpairs (hi + lo)
#pragma unroll
        for (int j = 0; j < 8; j++) {
            const int f = tid + j * 128;
            const int kk = f >> 4, p = f & 15;
            bh32[kk * 17 + p] = g_cbh[kk * 256 + (d0 >> 1) + p];
            bl32[kk * 17 + p] = g_cbl[kk * 256 + (d0 >> 1) + p];
        }
        __syncthreads();

#pragma unroll
        for (int c = 0; c < 2; c++) {
            const int co = c * 8 + tig;
            uint32_t AH[2][4], AL[2][4];
#pragma unroll
            for (int mt = 0; mt < 2; mt++) {
                const int ra = (w * 32 + mt * 16 + g) * 17;
                const int rb = ra + 8 * 17;
                AH[mt][0] = xh32[ra + co];     AH[mt][1] = xh32[rb + co];
                AH[mt][2] = xh32[ra + co + 4]; AH[mt][3] = xh32[rb + co + 4];
                AL[mt][0] = xl32[ra + co];     AL[mt][1] = xl32[rb + co];
                AL[mt][2] = xl32[ra + co + 4]; AL[mt][3] = xl32[rb + co + 4];
            }
#pragma unroll
            for (int j = 0; j < 8; j++) {
                const int kb = (8 * j + g) * 17;
                const uint32_t bh0 = bh32[kb + co], bh1 = bh32[kb + co + 4];
                const uint32_t bl0 = bl32[kb + co], bl1 = bl32[kb + co + 4];
#pragma unroll
                for (int mt = 0; mt < 2; mt++) {
                    mma16816(acc[mt][j], AH[mt][0], AH[mt][1], AH[mt][2], AH[mt][3], bh0, bh1);
                    mma16816(acc[mt][j], AL[mt][0], AL[mt][1], AL[mt][2], AL[mt][3], bh0, bh1);
                    mma16816(acc[mt][j], AH[mt][0], AH[mt][1], AH[mt][2], AH[mt][3], bl0, bl1);
                }
            }
        }
        __syncthreads();
    }

    // --- softmax per m-tile: rows (w*32+mt*16+g) and (+8), quad-owned ---
#pragma unroll
    for (int mt = 0; mt < 2; mt++) {
        float m0 = -1e30f, m1 = -1e30f;
#pragma unroll
        for (int j = 0; j < 8; j++) {
            m0 = fmaxf(m0, fmaxf(acc[mt][j][0], acc[mt][j][1]));
            m1 = fmaxf(m1, fmaxf(acc[mt][j][2], acc[mt][j][3]));
        }
        m0 = fmaxf(m0, __shfl_xor_sync(0xffffffffu, m0, 1));
        m0 = fmaxf(m0, __shfl_xor_sync(0xffffffffu, m0, 2));
        m1 = fmaxf(m1, __shfl_xor_sync(0xffffffffu, m1, 1));
        m1 = fmaxf(m1, __shfl_xor_sync(0xffffffffu, m1, 2));
        float s0 = 0.f, s1 = 0.f;
#pragma unroll
        for (int j = 0; j < 8; j++) {
            acc[mt][j][0] = __expf(acc[mt][j][0] - m0); s0 += acc[mt][j][0];
            acc[mt][j][1] = __expf(acc[mt][j][1] - m0); s0 += acc[mt][j][1];
            acc[mt][j][2] = __expf(acc[mt][j][2] - m1); s1 += acc[mt][j][2];
            acc[mt][j][3] = __expf(acc[mt][j][3] - m1); s1 += acc[mt][j][3];
        }
        s0 += __shfl_xor_sync(0xffffffffu, s0, 1);
        s0 += __shfl_xor_sync(0xffffffffu, s0, 2);
        s1 += __shfl_xor_sync(0xffffffffu, s1, 1);
        s1 += __shfl_xor_sync(0xffffffffu, s1, 2);
        const float i0 = 1.f / s0, i1 = 1.f / s1;
#pragma unroll
        for (int j = 0; j < 8; j++) {
            acc[mt][j][0] *= i0; acc[mt][j][1] *= i0;
            acc[mt][j][2] *= i1; acc[mt][j][3] *= i1;
        }
    }

    // --- a_sum column partials over this warp's 32 rows ---
#pragma unroll
    for (int j = 0; j < 8; j++) {
        float c0 = acc[0][j][0] + acc[0][j][2] + acc[1][j][0] + acc[1][j][2];
        float c1 = acc[0][j][1] + acc[0][j][3] + acc[1][j][1] + acc[1][j][3];
        c0 += __shfl_xor_sync(0xffffffffu, c0, 4);
        c0 += __shfl_xor_sync(0xffffffffu, c0, 8);
        c0 += __shfl_xor_sync(0xffffffffu, c0, 16);
        c1 += __shfl_xor_sync(0xffffffffu, c1, 4);
        c1 += __shfl_xor_sync(0xffffffffu, c1, 8);
        c1 += __shfl_xor_sync(0xffffffffu, c1, 16);
        if (lane < 4) {
            redp[w * 64 + 8 * j + 2 * tig]     = c0;
            redp[w * 64 + 8 * j + 2 * tig + 1] = c1;
        }
    }

    // --- write aT[b][k][n] as packed bf16 hi/lo (n-pairs via shfl_xor 4) ---
    const long bk = (long)b * 64;
#pragma unroll
    for (int mt = 0; mt < 2; mt++) {
#pragma unroll
        for (int j = 0; j < 8; j++) {
#pragma unroll
            for (int s = 0; s < 2; s++) {
#pragma unroll
                for (int rg = 0; rg < 2; rg++) {
                    const float v  = acc[mt][j][s + rg * 2];
                    const float pv = __shfl_xor_sync(0xffffffffu, v, 4);
                    if ((g & 1) == 0) {
                        uint32_t h, l;
                        split2(v, pv, h, l);
                        const int k = 8 * j + 2 * tig + s;
                        const int np = nb2 + w * 16 + mt * 8 + (g >> 1) + rg * 4;
                        g_aTh[(bk + k) * (NN / 2) + np] = h;
                        g_aTl[(bk + k) * (NN / 2) + np] = l;
                    }
                }
            }
        }
    }

    __syncthreads();
    if (tid < 64)
        g_asum_p[(long)blockIdx.x * 64 + tid] =
            redp[tid] + redp[64 + tid] + redp[128 + tid] + redp[192 + tid];
}

// ---------------------------------------------------------------------------
// K3: vlad D[d][k] = sum_n x[n,d]*a[n,k] via mma.sync bf16x3.
// Grid (8 dtiles, 64 b), 128 threads. Warp: 1 m16 d-tile x 8 n8 k-tiles.
// Fused residual + out write + ss partials.
// ---------------------------------------------------------------------------
__global__ __launch_bounds__(128) void k_vlad(const float* __restrict__ x,
                                              const float* __restrict__ c2,
                                              float* __restrict__ out) {
    __shared__ uint32_t xTh[64 * 17], xTl[64 * 17];
    __shared__ uint32_t aTh[64 * 17], aTl[64 * 17];
    __shared__ float    asum_s[64];
    __shared__ float    red[4 * 64];

    const int tid  = threadIdx.x;
    const int w    = tid >> 5;
    const int lane = tid & 31;
    const int g    = lane >> 2;
    const int tig  = lane & 3;
    const int b    = blockIdx.y;
    const int dt0  = blockIdx.x * 64;

    if (tid < 64) {
        float s = 0.f;
#pragma unroll
        for (int p = 0; p < 8; p++) s += g_asum_p[(long)(b * 8 + p) * 64 + tid];
        asum_s[tid] = s;
    }

    float acc[8][4];
#pragma unroll
    for (int j = 0; j < 8; j++)
#pragma unroll
        for (int q = 0; q < 4; q++) acc[j][q] = 0.f;

    const float* xb = x + (long)b * NN * DD;
    const long abase = (long)b * 64 * (NN / 2);

    for (int n0 = 0; n0 < NN; n0 += 32) {
        // xT tile: 64 d x 16 n-pairs, transpose+split during load
#pragma unroll
        for (int j = 0; j < 8; j++) {
            const int u = tid + j * 128;
            const int d = u & 63, i = u >> 6;
            const float v0 = xb[(n0 + 2 * i)     * DD + dt0 + d];
            const float v1 = xb[(n0 + 2 * i + 1) * DD + dt0 + d];
            uint32_t h, l;
            split2(v0, v1, h, l);
            xTh[d * 17 + i] = h;
            xTl[d * 17 + i] = l;
        }
        // aT tile: 64 k x 16 n-pairs (already packed in gmem)
#pragma unroll
        for (int j = 0; j < 8; j++) {
            const int u = tid + j * 128;
            const int kk = u >> 4, i = u & 15;
            aTh[kk * 17 + i] = g_aTh[abase + (long)kk * (NN / 2) + (n0 >> 1) + i];
            aTl[kk * 17 + i] = g_aTl[abase + (long)kk * (NN / 2) + (n0 >> 1) + i];
        }
        __syncthreads();

#pragma unroll
        for (int c = 0; c < 2; c++) {
            const int co = c * 8 + tig;
            const int ra = (w * 16 + g) * 17, rb = (w * 16 + g + 8) * 17;
            const uint32_t ah0 = xTh[ra + co],     ah1 = xTh[rb + co];
            const uint32_t ah2 = xTh[ra + co + 4], ah3 = xTh[rb + co + 4];
            const uint32_t al0 = xTl[ra + co],     al1 = xTl[rb + co];
            const uint32_t al2 = xTl[ra + co + 4], al3 = xTl[rb + co + 4];
#pragma unroll
            for (int j = 0; j < 8; j++) {
                const int kb = (8 * j + g) * 17;
                const uint32_t bh0 = aTh[kb + co], bh1 = aTh[kb + co + 4];
                const uint32_t bl0 = aTl[kb + co], bl1 = aTl[kb + co + 4];
                mma16816(acc[j], ah0, ah1, ah2, ah3, bh0, bh1);
                mma16816(acc[j], al0, al1, al2, al3, bh0, bh1);
                mma16816(acc[j], ah0, ah1, ah2, ah3, bl0, bl1);
            }
        }
        __syncthreads();
    }

    // --- epilogue: residual, write out[d][k], ss partials ---
    const int dg0 = dt0 + w * 16 + g;
    const int dg1 = dg0 + 8;
    float* ob = out + (long)b * DD * KK;

#pragma unroll
    for (int j = 0; j < 8; j++) {
        const int k = 8 * j + 2 * tig;
        const float as0 = asum_s[k], as1 = asum_s[k + 1];
        const float2 c2a = *(const float2*)&c2[dg0 * KK + k];
        const float2 c2b = *(const float2*)&c2[dg1 * KK + k];
        float v00 = acc[j][0] - as0 * c2a.x;
        float v01 = acc[j][1] - as1 * c2a.y;
        float v10 = acc[j][2] - as0 * c2b.x;
        float v11 = acc[j][3] - as1 * c2b.y;
        *(float2*)&ob[(long)dg0 * KK + k] = make_float2(v00, v01);
        *(float2*)&ob[(long)dg1 * KK + k] = make_float2(v10, v11);

        float ss0 = v00 * v00 + v10 * v10;
        float ss1 = v01 * v01 + v11 * v11;
        ss0 += __shfl_xor_sync(0xffffffffu, ss0, 4);
        ss0 += __shfl_xor_sync(0xffffffffu, ss0, 8);
        ss0 += __shfl_xor_sync(0xffffffffu, ss0, 16);
        ss1 += __shfl_xor_sync(0xffffffffu, ss1, 4);
        ss1 += __shfl_xor_sync(0xffffffffu, ss1, 8);
        ss1 += __shfl_xor_sync(0xffffffffu, ss1, 16);
        if (lane < 4) {
            red[w * 64 + k]     = ss0;
            red[w * 64 + k + 1] = ss1;
        }
    }
    __syncthreads();
    if (tid < 64)
        g_ss[(long)(b * 8 + blockIdx.x) * 64 + tid] =
            red[tid] + red[64 + tid] + red[128 + tid] + red[192 + tid];
}

// ---------------------------------------------------------------------------
// K4: per-(b,dtile) recompute tiny scale factors, rescale in place.
// ---------------------------------------------------------------------------
__global__ __launch_bounds__(256) void k_scale(float* __restrict__ out) {
    __shared__ float sc[64];
    __shared__ float nu2[64];
    __shared__ float wsum[2];

    const int b  = blockIdx.y;
    const int dt = blockIdx.x;
    const int t  = threadIdx.x;

    if (t < 64) {
        float s2 = 0.f;
#pragma unroll
        for (int p = 0; p < 8; p++) s2 += g_ss[(long)(b * 8 + p) * 64 + t];
        const float n  = sqrtf(s2);
        const float cv = 1.f / fmaxf(n, 1e-12f);
        const float nu = n * cv;
        sc[t]  = cv;
        nu2[t] = nu * nu;
    }
    __syncthreads();
    if (t < 64) {
        float wv = nu2[t];
#pragma unroll
        for (int o = 16; o; o >>= 1) wv += __shfl_xor_sync(0xffffffffu, wv, o);
        if ((t & 31) == 0) wsum[t >> 5] = wv;
    }
    __syncthreads();
    const float ginv = 1.f / fmaxf(sqrtf(wsum[0] + wsum[1]), 1e-12f);

    float4* p = (float4*)(out + ((long)b * DD + dt * 64) * KK);
#pragma unroll
    for (int j = 0; j < 4; j++) {
        const int idx = t + j * 256;
        const int k4 = (idx & 15) * 4;
        float4 v = p[idx];
        v.x *= sc[k4]     * ginv;
        v.y *= sc[k4 + 1] * ginv;
        v.z *= sc[k4 + 2] * ginv;
        v.w *= sc[k4 + 3] * ginv;
        p[idx] = v;
    }
}

// ---------------------------------------------------------------------------
extern "C" void kernel_launch(void* const* d_in, const int* in_sizes, int n_in,
                              void* d_out, int out_size) {
    const float* x        = (const float*)d_in[0];
    const float* clusters = (const float*)d_in[1];
    const float* bn_w     = (const float*)d_in[2];
    const float* bn_var   = (const float*)d_in[5];
    const float* c2       = (const float*)d_in[6];
    float* out = (float*)d_out;

    k_prep<<<64, 256>>>(clusters, bn_w, bn_var);
    k_assign<<<ROWS / 128, 128>>>(x);
    dim3 gv(DD / 64, BB);
    k_vlad<<<gv, 128>>>(x, c2, out);
    dim3 gs(DD / 64, BB);
    k_scale<<<gs, 256>>>(out);
}